// round 7
// baseline (speedup 1.0000x reference)
#include <cuda_runtime.h>
#include <cuda_bf16.h>
#include <math.h>

// Problem constants
#define BB   256
#define TT   512
#define EE   128
#define HD   128      // per-direction hidden
#define G4   512      // 4*HD
#define TAG  20
#define NCHAR 20000

typedef unsigned long long ull;

// packed f32x2 fma: acc = a*b + acc (elementwise on 2 packed floats)
#define FMA2(acc, a, b) asm("fma.rn.f32x2 %0, %1, %2, %0;" : "+l"(acc) : "l"(a), "l"(b))

__device__ __forceinline__ float pair_sum(ull u) {
    return __uint_as_float((unsigned)u) + __uint_as_float((unsigned)(u >> 32));
}
__device__ __forceinline__ float fast_tanh(float x) {
    float y;
    asm("tanh.approx.f32 %0, %1;" : "=f"(y) : "f"(x));
    return y;
}
__device__ __forceinline__ float fast_sigmoid(float x) {
    // sigmoid(x) = 0.5*tanh(0.5x) + 0.5  (1 MUFU + 2 FMA)
    return fmaf(0.5f, fast_tanh(0.5f * x), 0.5f);
}

// -------- scratch (device globals; no runtime allocation) --------
__device__ float g_xw_f[(size_t)NCHAR * G4];       // per-char input gates, fwd (41MB)
__device__ float g_xw_b[(size_t)NCHAR * G4];       // per-char input gates, bwd (41MB)
__device__ float g_score_f[(size_t)TT * BB * TAG]; // fwd-direction emission part
__device__ float g_score_b[(size_t)TT * BB * TAG]; // bwd-direction emission part
__device__ float g_loss[BB];

// no-op kernel: shifts ncu's fixed capture slot onto k2_lstm
__global__ void k_nop() {}

// =================================================================
// K1: per-character input projection tables (k-split layout)
//   xw_d[c][j] = sum_k emb[c][k]*Wih_d[j][k] + bih[j] + bhh[j]
// 128 CTAs = 16 chunks (dir*8 + 64-row jblock) x 8 cg-groups.
// Thread (w,l): ks=l&3 (k-slice of 32), id=w*8+(l>>2): cg4=id>>4
// (4-char group), rg=id&15 (4-row group). Weights in regs.
// =================================================================
__global__ __launch_bounds__(256, 1) void k1_xw(
    const float* __restrict__ emb,
    const float* __restrict__ wih_f, const float* __restrict__ wih_b,
    const float* __restrict__ bih_f, const float* __restrict__ bhh_f,
    const float* __restrict__ bih_b, const float* __restrict__ bhh_b)
{
    __shared__ float esm[16 * 128];   // 16 chars' embeddings

    int tid   = threadIdx.x;
    int bid   = blockIdx.x;
    int chunk = bid & 15;
    int grp   = bid >> 4;
    int dir   = chunk >> 3;
    int jbase = (chunk & 7) * 64;
    const float* wih = dir ? wih_b : wih_f;
    float* xout = dir ? g_xw_b : g_xw_f;

    int w  = tid >> 5, l = tid & 31;
    int ks = l & 3;
    int id = w * 8 + (l >> 2);
    int cg4 = id >> 4;           // 0..3: chars cg4*4..+3 within the 16-group
    int rg  = id & 15;           // 0..15: rows jbase + rg*4..+3

    // weights in regs: 4 rows x 32 k (k-slice ks)
    ulonglong2 wreg[4][8];
#pragma unroll
    for (int r = 0; r < 4; r++)
#pragma unroll
        for (int q = 0; q < 8; q++)
            wreg[r][q] = ((const ulonglong2*)wih)[(size_t)(jbase + rg * 4 + r) * 32 + ks * 8 + q];

    float4 biasv;
    {
        const float4* b1 = (const float4*)(dir ? bih_b : bih_f);
        const float4* b2 = (const float4*)(dir ? bhh_b : bhh_f);
        float4 x = b1[(jbase >> 2) + rg], y = b2[(jbase >> 2) + rg];
        biasv = make_float4(x.x + y.x, x.y + y.y, x.z + y.z, x.w + y.w);
    }

    for (int cg = grp; cg < 1250; cg += 8) {
        __syncthreads();
        for (int i = tid; i < 512; i += 256)
            ((float4*)esm)[i] = ((const float4*)emb)[(size_t)cg * 512 + i];
        __syncthreads();

        ull acc[4][4];   // [char][row]
#pragma unroll
        for (int c = 0; c < 4; c++)
#pragma unroll
            for (int r = 0; r < 4; r++) acc[c][r] = 0ull;

        const ulonglong2* e2 = (const ulonglong2*)esm;
#pragma unroll
        for (int q = 0; q < 8; q++) {
            ulonglong2 ev[4];
#pragma unroll
            for (int c = 0; c < 4; c++)
                ev[c] = e2[(cg4 * 4 + c) * 32 + ks * 8 + q];
#pragma unroll
            for (int c = 0; c < 4; c++)
#pragma unroll
                for (int r = 0; r < 4; r++) {
                    FMA2(acc[c][r], wreg[r][q].x, ev[c].x);
                    FMA2(acc[c][r], wreg[r][q].y, ev[c].y);
                }
        }

        float a[4][4];
#pragma unroll
        for (int c = 0; c < 4; c++)
#pragma unroll
            for (int r = 0; r < 4; r++) {
                float v = pair_sum(acc[c][r]);
                v += __shfl_xor_sync(0xffffffffu, v, 1);
                v += __shfl_xor_sync(0xffffffffu, v, 2);
                a[c][r] = v;
            }

        // lane ks owns char index ks of this 4-char group
        float4 o;
        o.x = a[ks][0] + biasv.x;
        o.y = a[ks][1] + biasv.y;
        o.z = a[ks][2] + biasv.z;
        o.w = a[ks][3] + biasv.w;
        int ch = cg * 16 + cg4 * 4 + ks;
        ((float4*)xout)[(size_t)ch * 128 + (jbase >> 2) + rg] = o;
    }
}

// =================================================================
// K2: BiLSTM recurrence + fused emission partials (k-split layout)
// grid 128: bid<64 -> forward, batches 4*bid..+3; bid>=64 -> backward.
// 256 threads. Warp w covers gate rows [w*64, w*64+64).
// Lane l: rg=l>>2, ks=l&3. Thread rows: w*64+rg*8+{0..7},
// k-slice ks*32..+31. Rows +0..3 weights in regs, +4..7 in smem.
// Partials reduced over ks via 2 shfl_xor rounds.
// rows 0..127=i, 128..255=f, 256..383=g, 384..511=o.
// =================================================================
#define NB 4
#define K2_SMEM_FLOATS (32768 + TAG * 128 + NB * 128 + NB * 512)
#define K2_SMEM_BYTES  (K2_SMEM_FLOATS * 4)

__global__ __launch_bounds__(256, 1) void k2_lstm(
    const int*   __restrict__ chars,
    const float* __restrict__ whh_f, const float* __restrict__ whh_b,
    const float* __restrict__ wlin)
{
    extern __shared__ float sm[];
    float* wsm = sm;            // 32768 floats: smem weight half, [w][ro][q][lane] float4
    float* wl  = sm + 32768;    // 2560 : W_lin direction half
    float* hsm = sm + 35328;    // [nb][128]
    float* gsm = sm + 35840;    // [nb][512] activated gate exchange

    int tid  = threadIdx.x;
    int bid  = blockIdx.x;
    int dir  = bid >> 6;
    int b0   = (bid & 63) * NB;
    const float* whh = dir ? whh_b : whh_f;
    const float* xw  = dir ? g_xw_b : g_xw_f;
    float* so        = dir ? g_score_b : g_score_f;

    int w  = tid >> 5, l = tid & 31;
    int rg = l >> 2, ks = l & 3;
    int row_base = w * 64 + rg * 8;

    // stage smem weight half: rows row_base+4..7 for every (w,rg), k-slice per ks.
    // float4 slot i = ((w*4+ro)*8+q)*32 + lane  <-  whh[row][k4]
    for (int i = tid; i < 8192; i += 256) {
        int ll = i & 31, q = (i >> 5) & 7, ro = (i >> 8) & 3, ww = i >> 10;
        int rrg = ll >> 2, kks = ll & 3;
        int row = ww * 64 + rrg * 8 + 4 + ro;
        int k4  = kks * 8 + q;
        ((float4*)wsm)[i] = ((const float4*)whh)[(size_t)row * 32 + k4];
    }
    for (int i = tid; i < TAG * 128; i += 256) {
        int tg = i >> 7, k = i & 127;
        wl[i] = wlin[tg * 256 + dir * 128 + k];
    }
    for (int i = tid; i < NB * 128; i += 256) hsm[i] = 0.f;

    // register weight half: rows row_base+0..3, 32 k each
    ulonglong2 wreg[4][8];
#pragma unroll
    for (int r = 0; r < 4; r++)
#pragma unroll
        for (int q = 0; q < 8; q++)
            wreg[r][q] = ((const ulonglong2*)whh)[(size_t)(row_base + r) * 32 + ks * 8 + q];
    __syncthreads();

    // c-update ownership: u = tid&127, nb pair = tid>>7
    int u  = tid & 127;
    int np = tid >> 7;
    float creg[2] = {0.f, 0.f};

    int cid[NB];
#pragma unroll
    for (int nb = 0; nb < NB; nb++)
        cid[nb] = __ldg(&chars[(b0 + nb) * TT + (dir ? TT - 1 : 0)]);

    const ulonglong2* h4  = (const ulonglong2*)hsm;
    const ulonglong2* w4s = (const ulonglong2*)wsm;

    for (int step = 0; step < TT; step++) {
        int t  = dir ? (TT - 1 - step) : step;
        int tn = dir ? (t - 1) : (t + 1);

        int cidn[NB];
        if (step + 1 < TT) {
#pragma unroll
            for (int nb = 0; nb < NB; nb++)
                cidn[nb] = __ldg(&chars[(b0 + nb) * TT + tn]);
        }

        // input-gate gather for this lane's activation rows (row_base+2ks+{0,1})
        float xg[2][NB];
#pragma unroll
        for (int r2 = 0; r2 < 2; r2++)
#pragma unroll
            for (int nb = 0; nb < NB; nb++)
                xg[r2][nb] = __ldg(xw + (size_t)cid[nb] * G4 + row_base + 2 * ks + r2);

        ull acc[8][NB];
#pragma unroll
        for (int r = 0; r < 8; r++)
#pragma unroll
            for (int nb = 0; nb < NB; nb++) acc[r][nb] = 0ull;

#pragma unroll
        for (int q = 0; q < 8; q++) {
            ulonglong2 hh[NB];
#pragma unroll
            for (int nb = 0; nb < NB; nb++)
                hh[nb] = h4[nb * 32 + ks * 8 + q];
            ulonglong2 ws[4];
            int base = (w * 4 * 8 + q) * 32 + l;
#pragma unroll
            for (int ro = 0; ro < 4; ro++)
                ws[ro] = w4s[base + ro * 256];
#pragma unroll
            for (int r = 0; r < 4; r++)
#pragma unroll
                for (int nb = 0; nb < NB; nb++) {
                    FMA2(acc[r][nb], wreg[r][q].x, hh[nb].x);
                    FMA2(acc[r][nb], wreg[r][q].y, hh[nb].y);
                }
#pragma unroll
            for (int ro = 0; ro < 4; ro++)
#pragma unroll
                for (int nb = 0; nb < NB; nb++) {
                    FMA2(acc[4 + ro][nb], ws[ro].x, hh[nb].x);
                    FMA2(acc[4 + ro][nb], ws[ro].y, hh[nb].y);
                }
        }

        // reduce over the 4 ks lanes
        float a[8][NB];
#pragma unroll
        for (int r = 0; r < 8; r++)
#pragma unroll
            for (int nb = 0; nb < NB; nb++) {
                float v = pair_sum(acc[r][nb]);
                v += __shfl_xor_sync(0xffffffffu, v, 1);
                v += __shfl_xor_sync(0xffffffffu, v, 2);
                a[r][nb] = v;
            }

        // activation: lane owns local rows 2*ks, 2*ks+1. warp gate type = w>>1
        int gt = w >> 1;   // 0 i, 1 f, 2 g, 3 o
#pragma unroll
        for (int r2 = 0; r2 < 2; r2++) {
            int row = row_base + 2 * ks + r2;
#pragma unroll
            for (int nb = 0; nb < NB; nb++) {
                float s = a[2 * ks + r2][nb] + xg[r2][nb];
                float v = (gt == 2) ? fast_tanh(s) : fast_sigmoid(s);
                gsm[nb * 512 + row] = v;
            }
        }
        __syncthreads();

        // c/h update: every thread handles unit u for 2 batches
#pragma unroll
        for (int e = 0; e < 2; e++) {
            int nb = np * 2 + e;
            float iv = gsm[nb * 512 + u];
            float fv = gsm[nb * 512 + 128 + u];
            float gg = gsm[nb * 512 + 256 + u];
            float oo = gsm[nb * 512 + 384 + u];
            float mm = (cid[nb] > 0) ? 1.f : 0.f;
            float cn = (fv * creg[e] + iv * gg) * mm;
            creg[e] = cn;
            hsm[nb * 128 + u] = oo * fast_tanh(cn) * mm;
        }
        __syncthreads();

        // emission partials: 20 tags x 8 k-chunks over warps 0..4
        if (tid < 160) {
            int tg = tid >> 3, p = tid & 7;
#pragma unroll
            for (int nb = 0; nb < NB; nb++) {
                float s = 0.f;
#pragma unroll
                for (int q = 0; q < 4; q++) {
                    float4 w4 = ((const float4*)wl)[tg * 32 + p * 4 + q];
                    float4 hv = ((const float4*)(hsm + nb * 128))[p * 4 + q];
                    s += w4.x * hv.x + w4.y * hv.y + w4.z * hv.z + w4.w * hv.w;
                }
                s += __shfl_down_sync(0xffffffffu, s, 4, 8);
                s += __shfl_down_sync(0xffffffffu, s, 2, 8);
                s += __shfl_down_sync(0xffffffffu, s, 1, 8);
                if (p == 0)
                    so[((size_t)t * BB + (b0 + nb)) * TAG + tg] = s;
            }
        }

#pragma unroll
        for (int nb = 0; nb < NB; nb++) cid[nb] = cidn[nb];
    }
}

// =================================================================
// K3: CRF forward (log-partition) + partial-annotation gold score
// grid 128, block 64: warp w handles b = bid*2 + w; tag j on lane j.
// Sequence length precomputed (ballot/popc); emissions prefetched.
// =================================================================
__global__ __launch_bounds__(64) void k3_crf(
    const int*   __restrict__ chars,
    const float* __restrict__ tags,
    const float* __restrict__ blin,
    const float* __restrict__ trans)
{
    __shared__ float tr[TAG * 21];
    __shared__ float tst[TAG], tsp[TAG], bl[TAG];
    __shared__ float abuf[2][2][TAG];
    __shared__ float gbuf[2][2][TAG];
    __shared__ float mbuf[2][2][TAG];

    int tid = threadIdx.x, w = tid >> 5, j = tid & 31;
    for (int i = tid; i < TAG * TAG; i += 64) {
        int rr = i / TAG, cc = i % TAG;
        tr[rr * 21 + cc] = trans[i];
    }
    if (tid < TAG) {
        tst[tid] = trans[tid * TAG + 1];       // trans[j][START]
        tsp[tid] = trans[2 * TAG + tid];       // trans[STOP][k]
        bl[tid]  = blin[tid];
    }
    __syncthreads();

    int b = blockIdx.x * 2 + w;
    bool act = (j < TAG);

    // sequence length (valid prefix; min length is 256)
    int L = 256;
#pragma unroll
    for (int base = 256; base < 512; base += 32) {
        int c = chars[b * TT + base + j];
        unsigned bal = __ballot_sync(0xffffffffu, c > 0);
        L += __popc(bal);
    }

    // trans row for this tag into registers
    float trr[TAG];
#pragma unroll
    for (int k = 0; k < TAG; k++) trr[k] = act ? tr[j * 21 + k] : 0.f;

    int cur = 0;
    if (act) {
        float e0 = g_score_f[(size_t)b * TAG + j] + g_score_b[(size_t)b * TAG + j] + bl[j];
        float a0 = e0 + tst[j];
        float m0 = tags[((size_t)b * TT) * TAG + j];
        abuf[w][0][j] = a0;
        gbuf[w][0][j] = (m0 > 0.f) ? a0 : 0.f;
        mbuf[w][0][j] = m0;
    }
    __syncwarp();

    // prefetch t=1
    float nf = 0.f, nbv = 0.f, nm = 0.f;
    if (act && L > 1) {
        nf  = g_score_f[((size_t)1 * BB + b) * TAG + j];
        nbv = g_score_b[((size_t)1 * BB + b) * TAG + j];
        nm  = tags[((size_t)b * TT + 1) * TAG + j];
    }

    for (int t = 1; t < L; t++) {
        int nxt = cur ^ 1;
        if (act) {
            float emit  = nf + nbv + bl[j];
            float maskc = nm;
            if (t + 1 < TT) {   // prefetch next step (unused past L; always in-bounds)
                nf  = g_score_f[((size_t)(t + 1) * BB + b) * TAG + j];
                nbv = g_score_b[((size_t)(t + 1) * BB + b) * TAG + j];
                nm  = tags[((size_t)b * TT + t + 1) * TAG + j];
            }
            // ---- forward alpha ----
            float m = -1e30f;
#pragma unroll
            for (int k = 0; k < TAG; k++)
                m = fmaxf(m, abuf[w][cur][k] + trr[k]);
            float s = 0.f;
#pragma unroll
            for (int k = 0; k < TAG; k++)
                s += __expf(abuf[w][cur][k] + trr[k] - m);
            abuf[w][nxt][j] = emit + m + __logf(s);
            // ---- gold (partial annotation) ----
            float gv = 0.f;
            if (maskc > 0.f) {
                float gm = -1e30f;
#pragma unroll
                for (int k = 0; k < TAG; k++) {
                    float v = gbuf[w][cur][k] + trr[k];
                    gm = fmaxf(gm, (mbuf[w][cur][k] > 0.f) ? v : -1e30f);
                }
                if (gm > -1e29f) {
                    float gs = 0.f;
#pragma unroll
                    for (int k = 0; k < TAG; k++) {
                        if (mbuf[w][cur][k] > 0.f)
                            gs += __expf(gbuf[w][cur][k] + trr[k] - gm);
                    }
                    gv = emit + gm + __logf(gs);
                }
            }
            gbuf[w][nxt][j] = gv;
            mbuf[w][nxt][j] = maskc;
        }
        __syncwarp();
        cur = nxt;
    }

    // forward_score = lse_k(alpha[k] + trans[STOP][k])
    float av = act ? (abuf[w][cur][j] + tsp[j]) : -1e30f;
    float m = av;
#pragma unroll
    for (int o = 16; o; o >>= 1) m = fmaxf(m, __shfl_xor_sync(0xffffffffu, m, o));
    float p = (av > -1e29f) ? __expf(av - m) : 0.f;
#pragma unroll
    for (int o = 16; o; o >>= 1) p += __shfl_xor_sync(0xffffffffu, p, o);
    float fwd = m + __logf(p);

    // gold_score = masked lse over tags with gold != 0
    float gj = act ? gbuf[w][cur][j] : 0.f;
    float ms = (gj != 0.f) ? 1.f : 0.f;
    float gx = (ms > 0.f) ? (gj + tsp[j]) : -1e30f;
    float gmx = gx, cnt = ms;
#pragma unroll
    for (int o = 16; o; o >>= 1) {
        gmx = fmaxf(gmx, __shfl_xor_sync(0xffffffffu, gmx, o));
        cnt += __shfl_xor_sync(0xffffffffu, cnt, o);
    }
    float gp = (gx > -1e29f) ? __expf(gx - gmx) : 0.f;
#pragma unroll
    for (int o = 16; o; o >>= 1) gp += __shfl_xor_sync(0xffffffffu, gp, o);
    float gsc = (cnt > 0.f) ? (gmx + __logf(gp)) : 0.f;

    if (j == 0) g_loss[b] = fwd - gsc;
}

// =================================================================
// K4: deterministic fixed-order reduction of per-batch losses
// =================================================================
__global__ void k4_reduce(float* out)
{
    int tid = threadIdx.x;
    if (tid < 32) {
        float s = 0.f;
#pragma unroll
        for (int q = 0; q < 8; q++) s += g_loss[tid + 32 * q];
#pragma unroll
        for (int o = 16; o; o >>= 1) s += __shfl_xor_sync(0xffffffffu, s, o);
        if (tid == 0) out[0] = s;
    }
}

// =================================================================
extern "C" void kernel_launch(void* const* d_in, const int* in_sizes, int n_in,
                              void* d_out, int out_size)
{
    const int*   chars = (const int*)  d_in[0];
    const float* tags  = (const float*)d_in[1];
    const float* emb   = (const float*)d_in[2];
    const float* wih_f = (const float*)d_in[3];
    const float* whh_f = (const float*)d_in[4];
    const float* bih_f = (const float*)d_in[5];
    const float* bhh_f = (const float*)d_in[6];
    const float* wih_b = (const float*)d_in[7];
    const float* whh_b = (const float*)d_in[8];
    const float* bih_b = (const float*)d_in[9];
    const float* bhh_b = (const float*)d_in[10];
    const float* wlin  = (const float*)d_in[11];
    const float* blin  = (const float*)d_in[12];
    const float* trans = (const float*)d_in[13];

    cudaFuncSetAttribute(k2_lstm, cudaFuncAttributeMaxDynamicSharedMemorySize, K2_SMEM_BYTES);

    // Launch order steers ncu's fixed capture slot onto k2_lstm:
    // k1, nop, nop, [k2 <- captured], k3, k4
    k1_xw<<<128, 256>>>(emb, wih_f, wih_b, bih_f, bhh_f, bih_b, bhh_b);
    k_nop<<<1, 32>>>();
    k_nop<<<1, 32>>>();
    k2_lstm<<<128, 256, K2_SMEM_BYTES>>>(chars, whh_f, whh_b, wlin);
    k3_crf<<<128, 64>>>(chars, tags, blin, trans);
    k4_reduce<<<1, 32>>>((float*)d_out);
}

// round 8
// speedup vs baseline: 1.1416x; 1.1416x over previous
#include <cuda_runtime.h>
#include <cuda_bf16.h>
#include <math.h>

// Problem constants
#define BB   256
#define TT   512
#define EE   128
#define HD   128      // per-direction hidden
#define G4   512      // 4*HD
#define TAG  20
#define NCHAR 20000

typedef unsigned long long ull;

// packed f32x2 fma: acc = a*b + acc (elementwise on 2 packed floats)
#define FMA2(acc, a, b) asm("fma.rn.f32x2 %0, %1, %2, %0;" : "+l"(acc) : "l"(a), "l"(b))

__device__ __forceinline__ float pair_sum(ull u) {
    return __uint_as_float((unsigned)u) + __uint_as_float((unsigned)(u >> 32));
}
__device__ __forceinline__ float fast_tanh(float x) {
    float y;
    asm("tanh.approx.f32 %0, %1;" : "=f"(y) : "f"(x));
    return y;
}
__device__ __forceinline__ float fast_sigmoid(float x) {
    // sigmoid(x) = 0.5*tanh(0.5x) + 0.5  (1 MUFU + 2 FMA)
    return fmaf(0.5f, fast_tanh(0.5f * x), 0.5f);
}

// -------- scratch (device globals; no runtime allocation) --------
__device__ float g_xw_f[(size_t)NCHAR * G4];       // per-char input gates, fwd (41MB)
__device__ float g_xw_b[(size_t)NCHAR * G4];       // per-char input gates, bwd (41MB)
__device__ float g_score_f[(size_t)TT * BB * TAG]; // fwd-direction emission part
__device__ float g_score_b[(size_t)TT * BB * TAG]; // bwd-direction emission part
__device__ float g_loss[BB];

// no-op kernel: shifts ncu's fixed capture slot onto k2_lstm
__global__ void k_nop() {}

// =================================================================
// K1: per-character input projection tables (k-split layout)
// (verified in R7; unchanged)
// =================================================================
__global__ __launch_bounds__(256, 1) void k1_xw(
    const float* __restrict__ emb,
    const float* __restrict__ wih_f, const float* __restrict__ wih_b,
    const float* __restrict__ bih_f, const float* __restrict__ bhh_f,
    const float* __restrict__ bih_b, const float* __restrict__ bhh_b)
{
    __shared__ float esm[16 * 128];   // 16 chars' embeddings

    int tid   = threadIdx.x;
    int bid   = blockIdx.x;
    int chunk = bid & 15;
    int grp   = bid >> 4;
    int dir   = chunk >> 3;
    int jbase = (chunk & 7) * 64;
    const float* wih = dir ? wih_b : wih_f;
    float* xout = dir ? g_xw_b : g_xw_f;

    int w  = tid >> 5, l = tid & 31;
    int ks = l & 3;
    int id = w * 8 + (l >> 2);
    int cg4 = id >> 4;           // 0..3: chars cg4*4..+3 within the 16-group
    int rg  = id & 15;           // 0..15: rows jbase + rg*4..+3

    // weights in regs: 4 rows x 32 k (k-slice ks)
    ulonglong2 wreg[4][8];
#pragma unroll
    for (int r = 0; r < 4; r++)
#pragma unroll
        for (int q = 0; q < 8; q++)
            wreg[r][q] = ((const ulonglong2*)wih)[(size_t)(jbase + rg * 4 + r) * 32 + ks * 8 + q];

    float4 biasv;
    {
        const float4* b1 = (const float4*)(dir ? bih_b : bih_f);
        const float4* b2 = (const float4*)(dir ? bhh_b : bhh_f);
        float4 x = b1[(jbase >> 2) + rg], y = b2[(jbase >> 2) + rg];
        biasv = make_float4(x.x + y.x, x.y + y.y, x.z + y.z, x.w + y.w);
    }

    for (int cg = grp; cg < 1250; cg += 8) {
        __syncthreads();
        for (int i = tid; i < 512; i += 256)
            ((float4*)esm)[i] = ((const float4*)emb)[(size_t)cg * 512 + i];
        __syncthreads();

        ull acc[4][4];   // [char][row]
#pragma unroll
        for (int c = 0; c < 4; c++)
#pragma unroll
            for (int r = 0; r < 4; r++) acc[c][r] = 0ull;

        const ulonglong2* e2 = (const ulonglong2*)esm;
#pragma unroll
        for (int q = 0; q < 8; q++) {
            ulonglong2 ev[4];
#pragma unroll
            for (int c = 0; c < 4; c++)
                ev[c] = e2[(cg4 * 4 + c) * 32 + ks * 8 + q];
#pragma unroll
            for (int c = 0; c < 4; c++)
#pragma unroll
                for (int r = 0; r < 4; r++) {
                    FMA2(acc[c][r], wreg[r][q].x, ev[c].x);
                    FMA2(acc[c][r], wreg[r][q].y, ev[c].y);
                }
        }

        float a[4][4];
#pragma unroll
        for (int c = 0; c < 4; c++)
#pragma unroll
            for (int r = 0; r < 4; r++) {
                float v = pair_sum(acc[c][r]);
                v += __shfl_xor_sync(0xffffffffu, v, 1);
                v += __shfl_xor_sync(0xffffffffu, v, 2);
                a[c][r] = v;
            }

        // lane ks owns char index ks of this 4-char group
        float4 o;
        o.x = a[ks][0] + biasv.x;
        o.y = a[ks][1] + biasv.y;
        o.z = a[ks][2] + biasv.z;
        o.w = a[ks][3] + biasv.w;
        int ch = cg * 16 + cg4 * 4 + ks;
        ((float4*)xout)[(size_t)ch * 128 + (jbase >> 2) + rg] = o;
    }
}

// =================================================================
// K2: BiLSTM recurrence + fused emission partials (S=2 k-split)
// grid 128: bid<64 -> forward, batches 4*bid..+3; bid>=64 -> backward.
// 256 threads, 8 warps. Warp w: gate rows [w*64, w*64+64).
// Lane l: ks=l&1 (64-k slice), rp=l>>1. Thread rows: base=w*64+rp*4,
// rows base+0,1 weights in regs; base+2,3 from smem.
// C=4 batches per thread. Partials reduced across the ks pair with
// ONE shfl_xor butterfly. rows 0..127=i,128..255=f,256..383=g,384..511=o
// =================================================================
#define NB 4
#define K2_SMEM_FLOATS (32768 + TAG * 128 + NB * 128 + NB * 512)
#define K2_SMEM_BYTES  (K2_SMEM_FLOATS * 4)

__global__ __launch_bounds__(256, 1) void k2_lstm(
    const int*   __restrict__ chars,
    const float* __restrict__ whh_f, const float* __restrict__ whh_b,
    const float* __restrict__ wlin)
{
    extern __shared__ float sm[];
    float* wsm = sm;            // 32768 floats, 2 banks of 4096 float4 slots
    float* wl  = sm + 32768;    // 2560 : W_lin direction half
    float* hsm = sm + 35328;    // [nb][128]
    float* gsm = sm + 35840;    // [nb][512] activated gate exchange

    int tid  = threadIdx.x;
    int bid  = blockIdx.x;
    int dir  = bid >> 6;
    int b0   = (bid & 63) * NB;
    const float* whh = dir ? whh_b : whh_f;
    const float* xw  = dir ? g_xw_b : g_xw_f;
    float* so        = dir ? g_score_b : g_score_f;

    int w  = tid >> 5, l = tid & 31;
    int ks = l & 1, rp = l >> 1;
    int base = w * 64 + rp * 4;

    // stage smem weight banks: slot i = ((ro*8 + ww)*16 + q)*32 + ll (float4)
    //   row = ww*64 + (ll>>1)*4 + 2 + ro ; k-granule = (ll&1)*16 + q
    for (int i = tid; i < 8192; i += 256) {
        int ll = i & 31, q = (i >> 5) & 15, ww = (i >> 9) & 7, ro = i >> 12;
        int row = ww * 64 + (ll >> 1) * 4 + 2 + ro;
        int k4  = (ll & 1) * 16 + q;
        ((float4*)wsm)[i] = ((const float4*)whh)[(size_t)row * 32 + k4];
    }
    for (int i = tid; i < TAG * 128; i += 256) {
        int tg = i >> 7, k = i & 127;
        wl[i] = wlin[tg * 256 + dir * 128 + k];
    }
    for (int i = tid; i < NB * 128; i += 256) hsm[i] = 0.f;

    // register weight rows base+0, base+1 (k-slice ks): 2 x 16 x 16B = 128 regs
    ulonglong2 wreg[2][16];
#pragma unroll
    for (int r = 0; r < 2; r++)
#pragma unroll
        for (int q = 0; q < 16; q++)
            wreg[r][q] = ((const ulonglong2*)whh)[(size_t)(base + r) * 32 + ks * 16 + q];
    __syncthreads();

    // c-update ownership: unit u = tid&127, batch pair np = tid>>7
    int u  = tid & 127;
    int np = tid >> 7;
    float creg[2] = {0.f, 0.f};

    int cid[NB];
#pragma unroll
    for (int nb = 0; nb < NB; nb++)
        cid[nb] = __ldg(&chars[(b0 + nb) * TT + (dir ? TT - 1 : 0)]);

    const ulonglong2* h2p = (const ulonglong2*)hsm;
    const ulonglong2* w2s = (const ulonglong2*)wsm;
    int gt = w >> 1;   // 0 i, 1 f, 2 g, 3 o

    for (int step = 0; step < TT; step++) {
        int t  = dir ? (TT - 1 - step) : step;
        int tn = dir ? (t - 1) : (t + 1);

        int cidn[NB];
        if (step + 1 < TT) {
#pragma unroll
            for (int nb = 0; nb < NB; nb++)
                cidn[nb] = __ldg(&chars[(b0 + nb) * TT + tn]);
        }

        // input-gate gathers for this lane's activation rows: base+2*ks+{0,1}
        float xg[2][NB];
#pragma unroll
        for (int r2 = 0; r2 < 2; r2++)
#pragma unroll
            for (int nb = 0; nb < NB; nb++)
                xg[r2][nb] = __ldg(xw + (size_t)cid[nb] * G4 + base + 2 * ks + r2);

        ull acc[4][NB];
#pragma unroll
        for (int r = 0; r < 4; r++)
#pragma unroll
            for (int nb = 0; nb < NB; nb++) acc[r][nb] = 0ull;

#pragma unroll
        for (int q = 0; q < 16; q++) {
            ulonglong2 hh[NB];
#pragma unroll
            for (int nb = 0; nb < NB; nb++)
                hh[nb] = h2p[nb * 32 + ks * 16 + q];
            ulonglong2 ws2 = w2s[(w * 16 + q) * 32 + l];           // row base+2
            ulonglong2 ws3 = w2s[4096 + (w * 16 + q) * 32 + l];    // row base+3
#pragma unroll
            for (int nb = 0; nb < NB; nb++) {
                FMA2(acc[0][nb], wreg[0][q].x, hh[nb].x);
                FMA2(acc[0][nb], wreg[0][q].y, hh[nb].y);
                FMA2(acc[1][nb], wreg[1][q].x, hh[nb].x);
                FMA2(acc[1][nb], wreg[1][q].y, hh[nb].y);
                FMA2(acc[2][nb], ws2.x, hh[nb].x);
                FMA2(acc[2][nb], ws2.y, hh[nb].y);
                FMA2(acc[3][nb], ws3.x, hh[nb].x);
                FMA2(acc[3][nb], ws3.y, hh[nb].y);
            }
        }

        // butterfly reduce across the ks pair; lane ks keeps rows base+2*ks+{0,1}
        // (lane's k-slice partial of its own rows + partner's partial via 1 shfl)
#pragma unroll
        for (int r2 = 0; r2 < 2; r2++) {
#pragma unroll
            for (int nb = 0; nb < NB; nb++) {
                int r_mine = 2 * ks + r2;
                int r_oth  = 2 * (1 - ks) + r2;
                float p_mine = pair_sum(acc[r_mine][nb]);
                float p_send = pair_sum(acc[r_oth][nb]);
                float got = __shfl_xor_sync(0xffffffffu, p_send, 1);
                float s = p_mine + got + xg[r2][nb];
                float v = (gt == 2) ? fast_tanh(s) : fast_sigmoid(s);
                gsm[nb * 512 + base + 2 * ks + r2] = v;
            }
        }
        __syncthreads();

        // c/h update: every thread handles unit u for 2 batches
#pragma unroll
        for (int e = 0; e < 2; e++) {
            int nb = np * 2 + e;
            float iv = gsm[nb * 512 + u];
            float fv = gsm[nb * 512 + 128 + u];
            float gg = gsm[nb * 512 + 256 + u];
            float oo = gsm[nb * 512 + 384 + u];
            float mm = (cid[nb] > 0) ? 1.f : 0.f;
            float cn = (fv * creg[e] + iv * gg) * mm;
            creg[e] = cn;
            hsm[nb * 128 + u] = oo * fast_tanh(cn) * mm;
        }
        __syncthreads();

        // emission partials: 20 tags x 8 k-chunks over warps 0..4
        if (tid < 160) {
            int tg = tid >> 3, p = tid & 7;
#pragma unroll
            for (int nb = 0; nb < NB; nb++) {
                float s = 0.f;
#pragma unroll
                for (int q = 0; q < 4; q++) {
                    float4 w4 = ((const float4*)wl)[tg * 32 + p * 4 + q];
                    float4 hv = ((const float4*)(hsm + nb * 128))[p * 4 + q];
                    s += w4.x * hv.x + w4.y * hv.y + w4.z * hv.z + w4.w * hv.w;
                }
                s += __shfl_down_sync(0xffffffffu, s, 4, 8);
                s += __shfl_down_sync(0xffffffffu, s, 2, 8);
                s += __shfl_down_sync(0xffffffffu, s, 1, 8);
                if (p == 0)
                    so[((size_t)t * BB + (b0 + nb)) * TAG + tg] = s;
            }
        }

#pragma unroll
        for (int nb = 0; nb < NB; nb++) cid[nb] = cidn[nb];
    }
}

// =================================================================
// K3: CRF forward (log-partition) + partial-annotation gold score
// (verified in R7; unchanged)
// =================================================================
__global__ __launch_bounds__(64) void k3_crf(
    const int*   __restrict__ chars,
    const float* __restrict__ tags,
    const float* __restrict__ blin,
    const float* __restrict__ trans)
{
    __shared__ float tr[TAG * 21];
    __shared__ float tst[TAG], tsp[TAG], bl[TAG];
    __shared__ float abuf[2][2][TAG];
    __shared__ float gbuf[2][2][TAG];
    __shared__ float mbuf[2][2][TAG];

    int tid = threadIdx.x, w = tid >> 5, j = tid & 31;
    for (int i = tid; i < TAG * TAG; i += 64) {
        int rr = i / TAG, cc = i % TAG;
        tr[rr * 21 + cc] = trans[i];
    }
    if (tid < TAG) {
        tst[tid] = trans[tid * TAG + 1];       // trans[j][START]
        tsp[tid] = trans[2 * TAG + tid];       // trans[STOP][k]
        bl[tid]  = blin[tid];
    }
    __syncthreads();

    int b = blockIdx.x * 2 + w;
    bool act = (j < TAG);

    // sequence length (valid prefix; min length is 256)
    int L = 256;
#pragma unroll
    for (int base = 256; base < 512; base += 32) {
        int c = chars[b * TT + base + j];
        unsigned bal = __ballot_sync(0xffffffffu, c > 0);
        L += __popc(bal);
    }

    float trr[TAG];
#pragma unroll
    for (int k = 0; k < TAG; k++) trr[k] = act ? tr[j * 21 + k] : 0.f;

    int cur = 0;
    if (act) {
        float e0 = g_score_f[(size_t)b * TAG + j] + g_score_b[(size_t)b * TAG + j] + bl[j];
        float a0 = e0 + tst[j];
        float m0 = tags[((size_t)b * TT) * TAG + j];
        abuf[w][0][j] = a0;
        gbuf[w][0][j] = (m0 > 0.f) ? a0 : 0.f;
        mbuf[w][0][j] = m0;
    }
    __syncwarp();

    float nf = 0.f, nbv = 0.f, nm = 0.f;
    if (act && L > 1) {
        nf  = g_score_f[((size_t)1 * BB + b) * TAG + j];
        nbv = g_score_b[((size_t)1 * BB + b) * TAG + j];
        nm  = tags[((size_t)b * TT + 1) * TAG + j];
    }

    for (int t = 1; t < L; t++) {
        int nxt = cur ^ 1;
        if (act) {
            float emit  = nf + nbv + bl[j];
            float maskc = nm;
            if (t + 1 < TT) {
                nf  = g_score_f[((size_t)(t + 1) * BB + b) * TAG + j];
                nbv = g_score_b[((size_t)(t + 1) * BB + b) * TAG + j];
                nm  = tags[((size_t)b * TT + t + 1) * TAG + j];
            }
            float m = -1e30f;
#pragma unroll
            for (int k = 0; k < TAG; k++)
                m = fmaxf(m, abuf[w][cur][k] + trr[k]);
            float s = 0.f;
#pragma unroll
            for (int k = 0; k < TAG; k++)
                s += __expf(abuf[w][cur][k] + trr[k] - m);
            abuf[w][nxt][j] = emit + m + __logf(s);
            float gv = 0.f;
            if (maskc > 0.f) {
                float gm = -1e30f;
#pragma unroll
                for (int k = 0; k < TAG; k++) {
                    float v = gbuf[w][cur][k] + trr[k];
                    gm = fmaxf(gm, (mbuf[w][cur][k] > 0.f) ? v : -1e30f);
                }
                if (gm > -1e29f) {
                    float gs = 0.f;
#pragma unroll
                    for (int k = 0; k < TAG; k++) {
                        if (mbuf[w][cur][k] > 0.f)
                            gs += __expf(gbuf[w][cur][k] + trr[k] - gm);
                    }
                    gv = emit + gm + __logf(gs);
                }
            }
            gbuf[w][nxt][j] = gv;
            mbuf[w][nxt][j] = maskc;
        }
        __syncwarp();
        cur = nxt;
    }

    float av = act ? (abuf[w][cur][j] + tsp[j]) : -1e30f;
    float m = av;
#pragma unroll
    for (int o = 16; o; o >>= 1) m = fmaxf(m, __shfl_xor_sync(0xffffffffu, m, o));
    float p = (av > -1e29f) ? __expf(av - m) : 0.f;
#pragma unroll
    for (int o = 16; o; o >>= 1) p += __shfl_xor_sync(0xffffffffu, p, o);
    float fwd = m + __logf(p);

    float gj = act ? gbuf[w][cur][j] : 0.f;
    float ms = (gj != 0.f) ? 1.f : 0.f;
    float gx = (ms > 0.f) ? (gj + tsp[j]) : -1e30f;
    float gmx = gx, cnt = ms;
#pragma unroll
    for (int o = 16; o; o >>= 1) {
        gmx = fmaxf(gmx, __shfl_xor_sync(0xffffffffu, gmx, o));
        cnt += __shfl_xor_sync(0xffffffffu, cnt, o);
    }
    float gp = (gx > -1e29f) ? __expf(gx - gmx) : 0.f;
#pragma unroll
    for (int o = 16; o; o >>= 1) gp += __shfl_xor_sync(0xffffffffu, gp, o);
    float gsc = (cnt > 0.f) ? (gmx + __logf(gp)) : 0.f;

    if (j == 0) g_loss[b] = fwd - gsc;
}

// =================================================================
// K4: deterministic fixed-order reduction of per-batch losses
// =================================================================
__global__ void k4_reduce(float* out)
{
    int tid = threadIdx.x;
    if (tid < 32) {
        float s = 0.f;
#pragma unroll
        for (int q = 0; q < 8; q++) s += g_loss[tid + 32 * q];
#pragma unroll
        for (int o = 16; o; o >>= 1) s += __shfl_xor_sync(0xffffffffu, s, o);
        if (tid == 0) out[0] = s;
    }
}

// =================================================================
extern "C" void kernel_launch(void* const* d_in, const int* in_sizes, int n_in,
                              void* d_out, int out_size)
{
    const int*   chars = (const int*)  d_in[0];
    const float* tags  = (const float*)d_in[1];
    const float* emb   = (const float*)d_in[2];
    const float* wih_f = (const float*)d_in[3];
    const float* whh_f = (const float*)d_in[4];
    const float* bih_f = (const float*)d_in[5];
    const float* bhh_f = (const float*)d_in[6];
    const float* wih_b = (const float*)d_in[7];
    const float* whh_b = (const float*)d_in[8];
    const float* bih_b = (const float*)d_in[9];
    const float* bhh_b = (const float*)d_in[10];
    const float* wlin  = (const float*)d_in[11];
    const float* blin  = (const float*)d_in[12];
    const float* trans = (const float*)d_in[13];

    cudaFuncSetAttribute(k2_lstm, cudaFuncAttributeMaxDynamicSharedMemorySize, K2_SMEM_BYTES);

    // Launch order steers ncu's fixed capture slot onto k2_lstm:
    // k1, nop, nop, [k2 <- captured], k3, k4
    k1_xw<<<128, 256>>>(emb, wih_f, wih_b, bih_f, bhh_f, bih_b, bhh_b);
    k_nop<<<1, 32>>>();
    k_nop<<<1, 32>>>();
    k2_lstm<<<128, 256, K2_SMEM_BYTES>>>(chars, whh_f, whh_b, wlin);
    k3_crf<<<128, 64>>>(chars, tags, blin, trans);
    k4_reduce<<<1, 32>>>((float*)d_out);
}

// round 11
// speedup vs baseline: 1.3273x; 1.1627x over previous
#include <cuda_runtime.h>
#include <cuda_bf16.h>
#include <math.h>

// Problem constants
#define BB   256
#define TT   512
#define EE   128
#define HD   128      // per-direction hidden
#define G4   512      // 4*HD
#define TAG  20
#define NCHAR 20000

typedef unsigned long long ull;

// packed f32x2 fma: acc = a*b + acc (elementwise on 2 packed floats)
#define FMA2(acc, a, b) asm("fma.rn.f32x2 %0, %1, %2, %0;" : "+l"(acc) : "l"(a), "l"(b))

__device__ __forceinline__ float pair_sum(ull u) {
    return __uint_as_float((unsigned)u) + __uint_as_float((unsigned)(u >> 32));
}
__device__ __forceinline__ float fast_tanh(float x) {
    float y;
    asm("tanh.approx.f32 %0, %1;" : "=f"(y) : "f"(x));
    return y;
}
__device__ __forceinline__ float fast_sigmoid(float x) {
    return fmaf(0.5f, fast_tanh(0.5f * x), 0.5f);
}

// -------- scratch (device globals; no runtime allocation) --------
__device__ float g_xw_f[(size_t)NCHAR * G4];       // per-char input gates, fwd (41MB)
__device__ float g_xw_b[(size_t)NCHAR * G4];       // per-char input gates, bwd (41MB)
__device__ float g_score_f[(size_t)TT * BB * TAG]; // fwd-direction emission part
__device__ float g_score_b[(size_t)TT * BB * TAG]; // bwd-direction emission part
__device__ float g_loss[BB];

// padding kernel: shifts ncu's fixed capture slot onto k2_lstm
__global__ void k_pad() {}

// =================================================================
// K1: per-character input projection tables (k-split, double-buffered)
//   xw_d[c][j] = sum_k emb[c][k]*Wih_d[j][k] + bih[j] + bhh[j]
// =================================================================
__global__ __launch_bounds__(256, 1) void k1_xw(
    const float* __restrict__ emb,
    const float* __restrict__ wih_f, const float* __restrict__ wih_b,
    const float* __restrict__ bih_f, const float* __restrict__ bhh_f,
    const float* __restrict__ bih_b, const float* __restrict__ bhh_b)
{
    __shared__ float esm[2][16 * 128];   // double-buffered 16-char embedding groups

    int tid   = threadIdx.x;
    int bid   = blockIdx.x;
    int chunk = bid & 15;
    int grp   = bid >> 4;
    int dir   = chunk >> 3;
    int jbase = (chunk & 7) * 64;
    const float* wih = dir ? wih_b : wih_f;
    float* xout = dir ? g_xw_b : g_xw_f;

    int w  = tid >> 5, l = tid & 31;
    int ks = l & 3;
    int id = w * 8 + (l >> 2);
    int cg4 = id >> 4;           // 0..3: chars cg4*4..+3 within the 16-group
    int rg  = id & 15;           // 0..15: rows jbase + rg*4..+3

    // weights in regs: 4 rows x 32 k (k-slice ks)
    ulonglong2 wreg[4][8];
#pragma unroll
    for (int r = 0; r < 4; r++)
#pragma unroll
        for (int q = 0; q < 8; q++)
            wreg[r][q] = ((const ulonglong2*)wih)[(size_t)(jbase + rg * 4 + r) * 32 + ks * 8 + q];

    float4 biasv;
    {
        const float4* b1 = (const float4*)(dir ? bih_b : bih_f);
        const float4* b2 = (const float4*)(dir ? bhh_b : bhh_f);
        float4 x = b1[(jbase >> 2) + rg], y = b2[(jbase >> 2) + rg];
        biasv = make_float4(x.x + y.x, x.y + y.y, x.z + y.z, x.w + y.w);
    }

    // preload first group into buffer 0
    ((float4*)esm[0])[tid]       = ((const float4*)emb)[(size_t)grp * 512 + tid];
    ((float4*)esm[0])[tid + 256] = ((const float4*)emb)[(size_t)grp * 512 + tid + 256];
    int pb = 0;

    for (int cg = grp; cg < 1250; cg += 8) {
        __syncthreads();   // buffer pb ready; prior readers of pb^1 done

        // prefetch next group into regs (clamped; harmless duplicate on last iter)
        int cgn = (cg + 8 < 1250) ? cg + 8 : grp;
        float4 p0 = ((const float4*)emb)[(size_t)cgn * 512 + tid];
        float4 p1 = ((const float4*)emb)[(size_t)cgn * 512 + tid + 256];

        ull acc[4][4];   // [char][row]
#pragma unroll
        for (int c = 0; c < 4; c++)
#pragma unroll
            for (int r = 0; r < 4; r++) acc[c][r] = 0ull;

        const ulonglong2* e2 = (const ulonglong2*)esm[pb];
#pragma unroll
        for (int q = 0; q < 8; q++) {
            ulonglong2 ev[4];
#pragma unroll
            for (int c = 0; c < 4; c++)
                ev[c] = e2[(cg4 * 4 + c) * 32 + ks * 8 + q];
#pragma unroll
            for (int c = 0; c < 4; c++)
#pragma unroll
                for (int r = 0; r < 4; r++) {
                    FMA2(acc[c][r], wreg[r][q].x, ev[c].x);
                    FMA2(acc[c][r], wreg[r][q].y, ev[c].y);
                }
        }

        // store prefetch to the other buffer (readers waited at loop-top barrier)
        ((float4*)esm[pb ^ 1])[tid]       = p0;
        ((float4*)esm[pb ^ 1])[tid + 256] = p1;

        float a[4][4];
#pragma unroll
        for (int c = 0; c < 4; c++)
#pragma unroll
            for (int r = 0; r < 4; r++) {
                float v = pair_sum(acc[c][r]);
                v += __shfl_xor_sync(0xffffffffu, v, 1);
                v += __shfl_xor_sync(0xffffffffu, v, 2);
                a[c][r] = v;
            }

        float4 o;
        o.x = a[ks][0] + biasv.x;
        o.y = a[ks][1] + biasv.y;
        o.z = a[ks][2] + biasv.z;
        o.w = a[ks][3] + biasv.w;
        int ch = cg * 16 + cg4 * 4 + ks;
        ((float4*)xout)[(size_t)ch * 128 + (jbase >> 2) + rg] = o;
        pb ^= 1;
    }
}

// =================================================================
// K2: BiLSTM recurrence + fused emission partials.
// R6 gate-loop layout (proven fastest measured) + smem staging of
// chars and per-step xw gate inputs (kills the scalar-LDG storm the
// R6/R8 profile fit identified as the true k2 bottleneck).
// grid 128: bid<64 fwd batches 4*bid..+3; bid>=64 bwd.
// thread t: gate rows t (regs) and t+256 (smem).
// rows 0..127=i, 128..255=f, 256..383=g, 384..511=o.
// =================================================================
#define NB 4
// wb 32768 | wl 2560 | hsm 512 | psm 512 | xst 4096 | csm 2048(int)
#define K2_SMEM_FLOATS (32768 + 2560 + 512 + 512 + 4096 + 2048)
#define K2_SMEM_BYTES  (K2_SMEM_FLOATS * 4)

__global__ __launch_bounds__(256, 1) void k2_lstm(
    const int*   __restrict__ chars,
    const float* __restrict__ whh_f, const float* __restrict__ whh_b,
    const float* __restrict__ wlin)
{
    extern __shared__ float sm[];
    float* wb  = sm;            // 32768: [k4][row] float4 of rows 256..511
    float* wl  = sm + 32768;    // 2560 : W_lin direction half
    float* hsm = sm + 35328;    // [nb][128]
    float* psm = sm + 35840;    // [nb][128] i*g exchange
    float* xst = sm + 36352;    // 2 x [nb][512] staged gate inputs
    int*   csm = (int*)(sm + 40448);  // [nb][512] chars

    int tid  = threadIdx.x;
    int bid  = blockIdx.x;
    int dir  = bid >> 6;
    int b0   = (bid & 63) * NB;
    const float* whh = dir ? whh_b : whh_f;
    const float* xw  = dir ? g_xw_b : g_xw_f;
    float* so        = dir ? g_score_b : g_score_f;

    // smem weights: rows 256..511, layout [k4][r] float4 (conflict-free LDS.128)
    for (int i = tid; i < 32 * 256; i += 256) {
        int k4 = i >> 8, r = i & 255;
        ((float4*)wb)[i] = ((const float4*)whh)[(256 + r) * 32 + k4];
    }
    for (int i = tid; i < TAG * 128; i += 256) {
        int tg = i >> 7, k = i & 127;
        wl[i] = wlin[tg * 256 + dir * 128 + k];
    }
    for (int i = tid; i < NB * 32; i += 256)
        ((float4*)hsm)[i] = make_float4(0.f, 0.f, 0.f, 0.f);
    // chars for all NB batches, all steps (removes per-step chars LDG)
    for (int i = tid; i < NB * 512; i += 256)
        csm[i] = chars[(b0 + (i >> 9)) * TT + (i & 511)];

    // register weights for row tid, packed as 64 k-pairs
    ull waU[64];
#pragma unroll
    for (int p = 0; p < 64; p++) waU[p] = ((const ull*)whh)[(size_t)tid * 64 + p];

    // initial stage: xstage[0] for the first timestep
    {
        int t0 = dir ? TT - 1 : 0;
        int c0 = __ldg(&chars[(b0 + 0) * TT + t0]);
        int c1 = __ldg(&chars[(b0 + 1) * TT + t0]);
        int c2 = __ldg(&chars[(b0 + 2) * TT + t0]);
        int c3 = __ldg(&chars[(b0 + 3) * TT + t0]);
        int cc[4] = {c0, c1, c2, c3};
#pragma unroll
        for (int it = 0; it < 2; it++) {
            int s4 = tid + it * 256;        // float4 slot 0..511
            int nb = s4 >> 7, q = s4 & 127;
            ((float4*)xst)[s4] = __ldg(&((const float4*)(xw + (size_t)cc[nb] * G4))[q]);
        }
    }
    __syncthreads();

    float creg[NB];
#pragma unroll
    for (int nb = 0; nb < NB; nb++) creg[nb] = 0.f;

    const ulonglong2* wb4 = (const ulonglong2*)wb;
    int cur = 0;

    for (int step = 0; step < TT; step++) {
        int t = dir ? (TT - 1 - step) : step;

        // this step's gate inputs + masks from smem
        float xa[NB], xb[NB];
        int cid[NB];
#pragma unroll
        for (int nb = 0; nb < NB; nb++) {
            xa[nb]  = xst[cur * 2048 + nb * 512 + tid];
            xb[nb]  = xst[cur * 2048 + nb * 512 + 256 + tid];
            cid[nb] = csm[nb * 512 + t];
        }

        // prefetch next step's gate inputs (coalesced float4 LDG)
        float4 pf0, pf1;
        if (step + 1 < TT) {
            int tn = dir ? (t - 1) : (t + 1);
            int s0 = tid, s1 = tid + 256;
            int cn0 = csm[(s0 >> 7) * 512 + tn];
            int cn1 = csm[(s1 >> 7) * 512 + tn];
            pf0 = __ldg(&((const float4*)(xw + (size_t)cn0 * G4))[s0 & 127]);
            pf1 = __ldg(&((const float4*)(xw + (size_t)cn1 * G4))[s1 & 127]);
        }

        ull accA[NB], accB[NB];
#pragma unroll
        for (int nb = 0; nb < NB; nb++) { accA[nb] = 0ull; accB[nb] = 0ull; }

        const ulonglong2* h4p = (const ulonglong2*)hsm;
#pragma unroll
        for (int k4 = 0; k4 < 32; k4++) {
            ulonglong2 wB = wb4[k4 * 256 + tid];
            ull wA0 = waU[2 * k4], wA1 = waU[2 * k4 + 1];
#pragma unroll
            for (int nb = 0; nb < NB; nb++) {
                ulonglong2 h2 = h4p[nb * 32 + k4];
                FMA2(accA[nb], wA0, h2.x);
                FMA2(accA[nb], wA1, h2.y);
                FMA2(accB[nb], wB.x, h2.x);
                FMA2(accB[nb], wB.y, h2.y);
            }
        }

        float fv[NB], ov[NB];
#pragma unroll
        for (int nb = 0; nb < NB; nb++) {
            float aA = pair_sum(accA[nb]) + xa[nb];
            float aB = pair_sum(accB[nb]) + xb[nb];
            float sA = fast_sigmoid(aA);       // i (tid<128) / f (tid>=128)
            if (tid < 128) {
                psm[nb * 128 + tid] = sA * fast_tanh(aB);   // i*g
            } else {
                fv[nb] = sA;                    // f
                ov[nb] = fast_sigmoid(aB);      // o
            }
        }

        // commit prefetch to the other stage buffer before the barrier
        if (step + 1 < TT) {
            ((float4*)(xst + (cur ^ 1) * 2048))[tid]       = pf0;
            ((float4*)(xst + (cur ^ 1) * 2048))[tid + 256] = pf1;
        }
        __syncthreads();

        if (tid >= 128) {
            int u = tid - 128;
#pragma unroll
            for (int nb = 0; nb < NB; nb++) {
                float m  = (cid[nb] > 0) ? 1.f : 0.f;
                float cn = fv[nb] * creg[nb] + psm[nb * 128 + u];
                creg[nb] = cn * m;
                hsm[nb * 128 + u] = ov[nb] * fast_tanh(creg[nb]) * m;
            }
        }
        __syncthreads();

        // emission partials: 20 tags x 8 k-chunks over warps 0..4
        if (tid < 160) {
            int tg = tid >> 3, p = tid & 7;
#pragma unroll
            for (int nb = 0; nb < NB; nb++) {
                float s = 0.f;
#pragma unroll
                for (int q = 0; q < 4; q++) {
                    float4 w4 = ((const float4*)wl)[tg * 32 + p * 4 + q];
                    float4 hv = ((const float4*)(hsm + nb * 128))[p * 4 + q];
                    s += w4.x * hv.x + w4.y * hv.y + w4.z * hv.z + w4.w * hv.w;
                }
                s += __shfl_down_sync(0xffffffffu, s, 4, 8);
                s += __shfl_down_sync(0xffffffffu, s, 2, 8);
                s += __shfl_down_sync(0xffffffffu, s, 1, 8);
                if (p == 0)
                    so[((size_t)t * BB + (b0 + nb)) * TAG + tg] = s;
            }
        }
        cur ^= 1;
    }
}

// =================================================================
// K3: CRF forward (log-partition) + partial-annotation gold score
// grid 128, block 64: warp w handles b = bid*2 + w; tag j on lane j.
// =================================================================
__global__ __launch_bounds__(64) void k3_crf(
    const int*   __restrict__ chars,
    const float* __restrict__ tags,
    const float* __restrict__ blin,
    const float* __restrict__ trans)
{
    __shared__ float tr[TAG * 21];
    __shared__ float tst[TAG], tsp[TAG], bl[TAG];
    __shared__ float abuf[2][2][TAG];
    __shared__ float gbuf[2][2][TAG];
    __shared__ float mbuf[2][2][TAG];

    int tid = threadIdx.x, w = tid >> 5, j = tid & 31;
    for (int i = tid; i < TAG * TAG; i += 64) {
        int rr = i / TAG, cc = i % TAG;
        tr[rr * 21 + cc] = trans[i];
    }
    if (tid < TAG) {
        tst[tid] = trans[tid * TAG + 1];       // trans[j][START]
        tsp[tid] = trans[2 * TAG + tid];       // trans[STOP][k]
        bl[tid]  = blin[tid];
    }
    __syncthreads();

    int b = blockIdx.x * 2 + w;
    bool act = (j < TAG);

    int L = 256;
#pragma unroll
    for (int base = 256; base < 512; base += 32) {
        int c = chars[b * TT + base + j];
        unsigned bal = __ballot_sync(0xffffffffu, c > 0);
        L += __popc(bal);
    }

    float trr[TAG];
#pragma unroll
    for (int k = 0; k < TAG; k++) trr[k] = act ? tr[j * 21 + k] : 0.f;

    int cur = 0;
    if (act) {
        float e0 = g_score_f[(size_t)b * TAG + j] + g_score_b[(size_t)b * TAG + j] + bl[j];
        float a0 = e0 + tst[j];
        float m0 = tags[((size_t)b * TT) * TAG + j];
        abuf[w][0][j] = a0;
        gbuf[w][0][j] = (m0 > 0.f) ? a0 : 0.f;
        mbuf[w][0][j] = m0;
    }
    __syncwarp();

    float nf = 0.f, nbv = 0.f, nm = 0.f;
    if (act && L > 1) {
        nf  = g_score_f[((size_t)1 * BB + b) * TAG + j];
        nbv = g_score_b[((size_t)1 * BB + b) * TAG + j];
        nm  = tags[((size_t)b * TT + 1) * TAG + j];
    }

    for (int t = 1; t < L; t++) {
        int nxt = cur ^ 1;
        if (act) {
            float emit  = nf + nbv + bl[j];
            float maskc = nm;
            if (t + 1 < TT) {
                nf  = g_score_f[((size_t)(t + 1) * BB + b) * TAG + j];
                nbv = g_score_b[((size_t)(t + 1) * BB + b) * TAG + j];
                nm  = tags[((size_t)b * TT + t + 1) * TAG + j];
            }
            float m = -1e30f;
#pragma unroll
            for (int k = 0; k < TAG; k++)
                m = fmaxf(m, abuf[w][cur][k] + trr[k]);
            float s = 0.f;
#pragma unroll
            for (int k = 0; k < TAG; k++)
                s += __expf(abuf[w][cur][k] + trr[k] - m);
            abuf[w][nxt][j] = emit + m + __logf(s);
            float gv = 0.f;
            if (maskc > 0.f) {
                float gm = -1e30f;
#pragma unroll
                for (int k = 0; k < TAG; k++) {
                    float v = gbuf[w][cur][k] + trr[k];
                    gm = fmaxf(gm, (mbuf[w][cur][k] > 0.f) ? v : -1e30f);
                }
                if (gm > -1e29f) {
                    float gs = 0.f;
#pragma unroll
                    for (int k = 0; k < TAG; k++) {
                        if (mbuf[w][cur][k] > 0.f)
                            gs += __expf(gbuf[w][cur][k] + trr[k] - gm);
                    }
                    gv = emit + gm + __logf(gs);
                }
            }
            gbuf[w][nxt][j] = gv;
            mbuf[w][nxt][j] = maskc;
        }
        __syncwarp();
        cur = nxt;
    }

    float av = act ? (abuf[w][cur][j] + tsp[j]) : -1e30f;
    float m = av;
#pragma unroll
    for (int o = 16; o; o >>= 1) m = fmaxf(m, __shfl_xor_sync(0xffffffffu, m, o));
    float p = (av > -1e29f) ? __expf(av - m) : 0.f;
#pragma unroll
    for (int o = 16; o; o >>= 1) p += __shfl_xor_sync(0xffffffffu, p, o);
    float fwd = m + __logf(p);

    float gj = act ? gbuf[w][cur][j] : 0.f;
    float ms = (gj != 0.f) ? 1.f : 0.f;
    float gx = (ms > 0.f) ? (gj + tsp[j]) : -1e30f;
    float gmx = gx, cnt = ms;
#pragma unroll
    for (int o = 16; o; o >>= 1) {
        gmx = fmaxf(gmx, __shfl_xor_sync(0xffffffffu, gmx, o));
        cnt += __shfl_xor_sync(0xffffffffu, cnt, o);
    }
    float gp = (gx > -1e29f) ? __expf(gx - gmx) : 0.f;
#pragma unroll
    for (int o = 16; o; o >>= 1) gp += __shfl_xor_sync(0xffffffffu, gp, o);
    float gsc = (cnt > 0.f) ? (gmx + __logf(gp)) : 0.f;

    if (j == 0) g_loss[b] = fwd - gsc;
}

// =================================================================
// K4: deterministic fixed-order reduction of per-batch losses
// =================================================================
__global__ void k4_reduce(float* out)
{
    int tid = threadIdx.x;
    if (tid < 32) {
        float s = 0.f;
#pragma unroll
        for (int q = 0; q < 8; q++) s += g_loss[tid + 32 * q];
#pragma unroll
        for (int o = 16; o; o >>= 1) s += __shfl_xor_sync(0xffffffffu, s, o);
        if (tid == 0) out[0] = s;
    }
}

// =================================================================
extern "C" void kernel_launch(void* const* d_in, const int* in_sizes, int n_in,
                              void* d_out, int out_size)
{
    const int*   chars = (const int*)  d_in[0];
    const float* tags  = (const float*)d_in[1];
    const float* emb   = (const float*)d_in[2];
    const float* wih_f = (const float*)d_in[3];
    const float* whh_f = (const float*)d_in[4];
    const float* bih_f = (const float*)d_in[5];
    const float* bhh_f = (const float*)d_in[6];
    const float* wih_b = (const float*)d_in[7];
    const float* whh_b = (const float*)d_in[8];
    const float* bih_b = (const float*)d_in[9];
    const float* bhh_b = (const float*)d_in[10];
    const float* wlin  = (const float*)d_in[11];
    const float* blin  = (const float*)d_in[12];
    const float* trans = (const float*)d_in[13];

    cudaFuncSetAttribute(k2_lstm, cudaFuncAttributeMaxDynamicSharedMemorySize, K2_SMEM_BYTES);

    // Launch order steers ncu's fixed capture slot onto k2_lstm:
    // k1, pad, pad, [k2 <- captured], k3, k4
    k1_xw<<<128, 256>>>(emb, wih_f, wih_b, bih_f, bhh_f, bih_b, bhh_b);
    k_pad<<<1, 32>>>();
    k_pad<<<1, 32>>>();
    k2_lstm<<<128, 256, K2_SMEM_BYTES>>>(chars, whh_f, whh_b, wlin);
    k3_crf<<<128, 64>>>(chars, tags, blin, trans);
    k4_reduce<<<1, 32>>>((float*)d_out);
}